// round 2
// baseline (speedup 1.0000x reference)
#include <cuda_runtime.h>
#include <math.h>

// Problem constants
#define B_    2
#define Q_    75
#define WAY_  5
#define SHOT_ 5
#define HW_   100
#define C_    640
#define NK_   5

#define MROWS (Q_*HW_)        // 7500 query patches per b
#define NROWS (WAY_*HW_)      // 500 support patches per (b, group)
#define NGRP  (B_*SHOT_)      // 10 (b, group) GEMMs
#define NQTOT (B_*MROWS)      // 15000 query rows
#define NSTOT (NGRP*NROWS)    // 5000 support rows

// Scratch (static device globals — allocation-free per harness rules)
__device__ float g_invq[NQTOT];
__device__ float g_invs[NSTOT];
__device__ float g_scores[(size_t)NGRP * MROWS * NROWS];  // 37.5M floats = 150MB

// ---------------------------------------------------------------------------
// Kernel 1: inverse L2 norms. One warp per descriptor row (640 floats).
// Rows 0..14999 -> input1, rows 15000..19999 -> input2.
// ---------------------------------------------------------------------------
__global__ void norms_kernel(const float* __restrict__ q,
                             const float* __restrict__ s) {
    int warp = (blockIdx.x * blockDim.x + threadIdx.x) >> 5;
    int lane = threadIdx.x & 31;
    if (warp >= NQTOT + NSTOT) return;

    const float* src;
    float* dst;
    if (warp < NQTOT) {
        src = q + (size_t)warp * C_;
        dst = &g_invq[warp];
    } else {
        int r = warp - NQTOT;
        src = s + (size_t)r * C_;
        dst = &g_invs[r];
    }

    const float4* p4 = (const float4*)src;
    float acc = 0.f;
    #pragma unroll
    for (int i = lane; i < C_ / 4; i += 32) {
        float4 v = p4[i];
        acc += v.x * v.x + v.y * v.y + v.z * v.z + v.w * v.w;
    }
    #pragma unroll
    for (int o = 16; o; o >>= 1) acc += __shfl_xor_sync(0xFFFFFFFFu, acc, o);
    if (lane == 0) *dst = rsqrtf(acc);
}

// ---------------------------------------------------------------------------
// Kernel 2: batched SGEMM  C[z][m][n] = (A_b[m]·B_z[n]) * invq * invs
// A: [7500,640] row-major (per b), B: [500,640] row-major (per z=b*5+shot)
// Tile 128x128x16, 256 threads, 8x8 per-thread microtile.
// ---------------------------------------------------------------------------
#define BM 128
#define BN 128
#define BK 16
#define TM 8
#define TN 8

__global__ __launch_bounds__(256, 2)
void gemm_kernel(const float* __restrict__ Aall,
                 const float* __restrict__ Ball) {
    __shared__ float As[BK][BM];
    __shared__ float Bs[BK][BN];

    const int z = blockIdx.z;          // 0..9 : b*5 + group
    const int b = z / SHOT_;
    const int mBlock = blockIdx.y * BM;
    const int nBlock = blockIdx.x * BN;

    const float* A  = Aall + (size_t)b * MROWS * C_;
    const float* Bm = Ball + (size_t)z * NROWS * C_;
    float* Cout = g_scores + (size_t)z * MROWS * NROWS;

    const int tid = threadIdx.x;
    const int tx  = tid & 15;          // 0..15 (N dir)
    const int ty  = tid >> 4;          // 0..15 (M dir)

    float acc[TM][TN];
    #pragma unroll
    for (int i = 0; i < TM; i++)
        #pragma unroll
        for (int j = 0; j < TN; j++) acc[i][j] = 0.f;

    for (int kb = 0; kb < C_; kb += BK) {
        // Load A tile: 128 rows x 16 cols = 512 float4s, 2 per thread
        #pragma unroll
        for (int j = 0; j < 2; j++) {
            int f   = tid + 256 * j;
            int row = f >> 2;
            int kc  = f & 3;
            int gm  = mBlock + row;
            float4 v = make_float4(0.f, 0.f, 0.f, 0.f);
            if (gm < MROWS)
                v = *(const float4*)(A + (size_t)gm * C_ + kb + kc * 4);
            As[kc * 4 + 0][row] = v.x;
            As[kc * 4 + 1][row] = v.y;
            As[kc * 4 + 2][row] = v.z;
            As[kc * 4 + 3][row] = v.w;
        }
        // Load B tile
        #pragma unroll
        for (int j = 0; j < 2; j++) {
            int f   = tid + 256 * j;
            int row = f >> 2;
            int kc  = f & 3;
            int gn  = nBlock + row;
            float4 v = make_float4(0.f, 0.f, 0.f, 0.f);
            if (gn < NROWS)
                v = *(const float4*)(Bm + (size_t)gn * C_ + kb + kc * 4);
            Bs[kc * 4 + 0][row] = v.x;
            Bs[kc * 4 + 1][row] = v.y;
            Bs[kc * 4 + 2][row] = v.z;
            Bs[kc * 4 + 3][row] = v.w;
        }
        __syncthreads();

        #pragma unroll
        for (int k = 0; k < BK; k++) {
            float ra[TM], rb[TN];
            // vectorized shared loads (8 floats = 2 x float4, 32B aligned)
            float4 a0 = *(const float4*)&As[k][ty * TM];
            float4 a1 = *(const float4*)&As[k][ty * TM + 4];
            float4 b0 = *(const float4*)&Bs[k][tx * TN];
            float4 b1 = *(const float4*)&Bs[k][tx * TN + 4];
            ra[0]=a0.x; ra[1]=a0.y; ra[2]=a0.z; ra[3]=a0.w;
            ra[4]=a1.x; ra[5]=a1.y; ra[6]=a1.z; ra[7]=a1.w;
            rb[0]=b0.x; rb[1]=b0.y; rb[2]=b0.z; rb[3]=b0.w;
            rb[4]=b1.x; rb[5]=b1.y; rb[6]=b1.z; rb[7]=b1.w;
            #pragma unroll
            for (int i = 0; i < TM; i++)
                #pragma unroll
                for (int j = 0; j < TN; j++)
                    acc[i][j] = fmaf(ra[i], rb[j], acc[i][j]);
        }
        __syncthreads();
    }

    // Epilogue: scale by inverse norms, store (guarded)
    float iq[TM], is[TN];
    #pragma unroll
    for (int i = 0; i < TM; i++) {
        int gm = mBlock + ty * TM + i;
        iq[i] = (gm < MROWS) ? g_invq[b * MROWS + gm] : 0.f;
    }
    #pragma unroll
    for (int j = 0; j < TN; j++) {
        int gn = nBlock + tx * TN + j;
        is[j] = (gn < NROWS) ? g_invs[z * NROWS + gn] : 0.f;
    }
    #pragma unroll
    for (int i = 0; i < TM; i++) {
        int gm = mBlock + ty * TM + i;
        if (gm >= MROWS) continue;
        #pragma unroll
        for (int j = 0; j < TN; j++) {
            int gn = nBlock + tx * TN + j;
            if (gn < NROWS)
                Cout[(size_t)gm * NROWS + gn] = acc[i][j] * iq[i] * is[j];
        }
    }
}

// ---------------------------------------------------------------------------
// Kernel 3: per-row top-5 mean + reduction over the 100 query patches.
// One block per (b,q,way) output; warp per score row of 500.
// ---------------------------------------------------------------------------
__global__ void topk_kernel(float* __restrict__ out) {
    const int blk = blockIdx.x;            // = b*375 + q*5 + w
    const int w = blk % WAY_;
    const int q = (blk / WAY_) % Q_;
    const int b = blk / (Q_ * WAY_);
    const int z = b * SHOT_ + w;

    const float* base = g_scores + (size_t)z * MROWS * NROWS
                                 + (size_t)q * HW_ * NROWS;

    const int warp = threadIdx.x >> 5;     // 0..7
    const int lane = threadIdx.x & 31;
    __shared__ float partial[8];

    float acc = 0.f;
    for (int p = warp; p < HW_; p += 8) {
        const float* row = base + (size_t)p * NROWS;

        // local top-5 (sorted desc) over strided elements
        float t0 = -INFINITY, t1 = -INFINITY, t2 = -INFINITY,
              t3 = -INFINITY, t4 = -INFINITY;
        for (int i = lane; i < NROWS; i += 32) {
            float v = row[i];
            if (v > t4) {
                t4 = v;
                if (t4 > t3) { float x = t4; t4 = t3; t3 = x; }
                if (t3 > t2) { float x = t3; t3 = t2; t2 = x; }
                if (t2 > t1) { float x = t2; t2 = t1; t1 = x; }
                if (t1 > t0) { float x = t1; t1 = t0; t0 = x; }
            }
        }

        // warp merge: pop global max 5 times (each lane's list is sorted desc)
        float rsum = 0.f;
        #pragma unroll
        for (int r = 0; r < NK_; r++) {
            float cand = t0;
            float m = cand;
            #pragma unroll
            for (int o = 16; o; o >>= 1)
                m = fmaxf(m, __shfl_xor_sync(0xFFFFFFFFu, m, o));
            unsigned msk = __ballot_sync(0xFFFFFFFFu, cand == m);
            int owner = __ffs(msk) - 1;
            if (lane == owner) {            // pop head
                t0 = t1; t1 = t2; t2 = t3; t3 = t4; t4 = -INFINITY;
            }
            rsum += m;
        }
        acc += rsum * (1.0f / NK_);
    }

    if (lane == 0) partial[warp] = acc;
    __syncthreads();
    if (threadIdx.x == 0) {
        float s = 0.f;
        #pragma unroll
        for (int i = 0; i < 8; i++) s += partial[i];
        out[blk] = s;
    }
}

// ---------------------------------------------------------------------------
extern "C" void kernel_launch(void* const* d_in, const int* in_sizes, int n_in,
                              void* d_out, int out_size) {
    const float* input1 = (const float*)d_in[0];   // [2,75,10,10,640]
    const float* input2 = (const float*)d_in[1];   // [2,5,5,10,10,640]
    float* out = (float*)d_out;                    // [2,75,5] = 750

    // 1) inverse norms: 20000 warps -> 2500 blocks x 256
    norms_kernel<<<(NQTOT + NSTOT + 7) / 8, 256>>>(input1, input2);

    // 2) batched SGEMM with normalization epilogue
    dim3 g((NROWS + BN - 1) / BN, (MROWS + BM - 1) / BM, NGRP);  // (4,59,10)
    gemm_kernel<<<g, 256>>>(input1, input2);

    // 3) top-5 mean + patch reduction
    topk_kernel<<<B_ * Q_ * WAY_, 256>>>(out);
}

// round 4
// speedup vs baseline: 5.5772x; 5.5772x over previous
#include <cuda_runtime.h>
#include <cuda_bf16.h>
#include <math.h>
#include <stdint.h>

// Problem constants
#define B_    2
#define Q_    75
#define WAY_  5
#define SHOT_ 5
#define HW_   100
#define C_    640
#define NK_   5

#define MROWS (Q_*HW_)        // 7500 query patches per b
#define NROWS (WAY_*HW_)      // 500 support patches per group
#define NGRP  (B_*SHOT_)      // 10 groups
#define NQTOT (B_*MROWS)      // 15000
#define NSTOT (NGRP*NROWS)    // 5000

// Normalized bf16 descriptors (static device scratch — allocation-free)
__device__ __nv_bfloat16 g_q16[(size_t)NQTOT * C_];
__device__ __nv_bfloat16 g_s16[(size_t)NSTOT * C_];

__device__ __forceinline__ uint32_t smem_u32(const void* p) {
    uint32_t a;
    asm("{ .reg .u64 t; cvta.to.shared.u64 t, %1; cvt.u32.u64 %0, t; }"
        : "=r"(a) : "l"(p));
    return a;
}

#define SWZ128(o) ((o) ^ (((o) >> 3) & 0x70))

// ---------------------------------------------------------------------------
// Kernel 1: L2-normalize each 640-dim descriptor, cast to bf16.
// One warp per row (20000 rows).
// ---------------------------------------------------------------------------
__global__ void normalize_kernel(const float* __restrict__ q,
                                 const float* __restrict__ s) {
    int warp = (blockIdx.x * blockDim.x + threadIdx.x) >> 5;
    int lane = threadIdx.x & 31;
    if (warp >= NQTOT + NSTOT) return;

    const float* src;
    __nv_bfloat16* dst;
    if (warp < NQTOT) {
        src = q + (size_t)warp * C_;
        dst = g_q16 + (size_t)warp * C_;
    } else {
        int r = warp - NQTOT;
        src = s + (size_t)r * C_;
        dst = g_s16 + (size_t)r * C_;
    }

    const float4* p4 = (const float4*)src;
    float4 v[5];
    float acc = 0.f;
    #pragma unroll
    for (int t = 0; t < 5; t++) {
        v[t] = p4[lane + 32 * t];
        acc += v[t].x * v[t].x + v[t].y * v[t].y + v[t].z * v[t].z + v[t].w * v[t].w;
    }
    #pragma unroll
    for (int o = 16; o; o >>= 1) acc += __shfl_xor_sync(0xFFFFFFFFu, acc, o);
    float inv = rsqrtf(acc);

    #pragma unroll
    for (int t = 0; t < 5; t++) {
        __nv_bfloat162 lo = __float22bfloat162_rn(make_float2(v[t].x * inv, v[t].y * inv));
        __nv_bfloat162 hi = __float22bfloat162_rn(make_float2(v[t].z * inv, v[t].w * inv));
        uint2 pack;
        pack.x = *(uint32_t*)&lo;
        pack.y = *(uint32_t*)&hi;
        *(uint2*)(dst + (size_t)(lane + 32 * t) * 4) = pack;
    }
}

// ---------------------------------------------------------------------------
// Kernel 2: zero the 750-float output (poisoned before timing).
// ---------------------------------------------------------------------------
__global__ void zero_out_kernel(float* __restrict__ out) {
    int i = blockIdx.x * blockDim.x + threadIdx.x;
    if (i < B_ * Q_ * WAY_) out[i] = 0.f;
}

// ---------------------------------------------------------------------------
// Kernel 3: fused bf16 HMMA GEMM (128 x 512 x 640) + streaming top-5 + reduce.
// grid = (59 M-tiles, 10 groups), 256 threads (8 warps as 4x2).
// N processed in 4 chunks of 128; per-thread register top-5 per owned row.
// ---------------------------------------------------------------------------
#define BM   128
#define BNC  128           // N chunk
#define BK   64            // K chunk (64 bf16 = 128B rows, SW128)
#define NKC  (C_/BK)       // 10
#define NNC  4             // N chunks (covers 512 padded)

#define SA_OFF(buf) ((buf) * 16384)
#define SB_OFF(buf) (32768 + (buf) * 16384)
#define SMEM_TOTAL  65536

__global__ __launch_bounds__(256)
void fused_gemm_topk_kernel(float* __restrict__ out) {
    extern __shared__ __align__(1024) char smem[];
    const uint32_t sbase = smem_u32(smem);
    const int tid   = threadIdx.x;
    const int lane  = tid & 31;
    const int wid   = tid >> 5;
    const int warpM = wid >> 1;      // 0..3
    const int warpN = wid & 1;       // 0..1

    const int mBlock = blockIdx.x * BM;
    const int z   = blockIdx.y;      // b*5 + group
    const int b   = z / SHOT_;
    const int grp = z % SHOT_;

    const __nv_bfloat16* gA = g_q16 + (size_t)b * MROWS * C_;
    const __nv_bfloat16* gB = g_s16 + (size_t)z * NROWS * C_;

    // running top-5 per owned row: rr=0..3 -> row = warpM*32 + rr*8 + lane/4
    float t5[4][5];
    #pragma unroll
    for (int r = 0; r < 4; r++)
        #pragma unroll
        for (int j = 0; j < 5; j++) t5[r][j] = -INFINITY;

    // stage loader: A 128x64 bf16 + B 128x64 bf16, swizzled, zfill OOB
    auto load_stage = [&](int cb, int kc, int buf) {
        #pragma unroll
        for (int t = 0; t < 4; t++) {
            int u = tid + t * 256;
            int r = u >> 3, seg = u & 7;
            int gm = mBlock + r;
            uint32_t dst = sbase + SA_OFF(buf) + SWZ128(r * 128 + seg * 16);
            const char* src = (const char*)gA
                + ((size_t)(gm < MROWS ? gm : 0) * C_ + kc * BK) * 2 + seg * 16;
            int sz = (gm < MROWS) ? 16 : 0;
            asm volatile("cp.async.cg.shared.global [%0], [%1], 16, %2;"
                         :: "r"(dst), "l"(src), "r"(sz));
        }
        #pragma unroll
        for (int t = 0; t < 4; t++) {
            int u = tid + t * 256;
            int r = u >> 3, seg = u & 7;
            int gn = cb * BNC + r;
            uint32_t dst = sbase + SB_OFF(buf) + SWZ128(r * 128 + seg * 16);
            const char* src = (const char*)gB
                + ((size_t)(gn < NROWS ? gn : 0) * C_ + kc * BK) * 2 + seg * 16;
            int sz = (gn < NROWS) ? 16 : 0;
            asm volatile("cp.async.cg.shared.global [%0], [%1], 16, %2;"
                         :: "r"(dst), "l"(src), "r"(sz));
        }
        asm volatile("cp.async.commit_group;" ::: "memory");
    };

    #pragma unroll 1
    for (int cb = 0; cb < NNC; cb++) {
        float acc[2][8][4];
        #pragma unroll
        for (int mt = 0; mt < 2; mt++)
            #pragma unroll
            for (int nt = 0; nt < 8; nt++)
                #pragma unroll
                for (int c = 0; c < 4; c++) acc[mt][nt][c] = 0.f;

        load_stage(cb, 0, 0);

        #pragma unroll 1
        for (int kc = 0; kc < NKC; kc++) {
            const int buf = kc & 1;
            if (kc + 1 < NKC) {
                load_stage(cb, kc + 1, buf ^ 1);
                asm volatile("cp.async.wait_group 1;" ::: "memory");
            } else {
                asm volatile("cp.async.wait_group 0;" ::: "memory");
            }
            __syncthreads();

            const uint32_t sA = sbase + SA_OFF(buf);
            const uint32_t sB = sbase + SB_OFF(buf);

            #pragma unroll
            for (int ks = 0; ks < 4; ks++) {
                // A fragments (2 m-tiles of 16x16)
                uint32_t a[2][4];
                #pragma unroll
                for (int mt = 0; mt < 2; mt++) {
                    int row = warpM * 32 + mt * 16 + (lane & 15);
                    uint32_t ad = sA + SWZ128(row * 128 + ks * 32 + (lane >> 4) * 16);
                    asm volatile(
                        "ldmatrix.sync.aligned.m8n8.x4.shared.b16 {%0,%1,%2,%3}, [%4];"
                        : "=r"(a[mt][0]), "=r"(a[mt][1]), "=r"(a[mt][2]), "=r"(a[mt][3])
                        : "r"(ad));
                }
                // B fragments (4 x4-loads cover 8 n-tiles of 8)
                uint32_t bq[4][4];
                #pragma unroll
                for (int nt2 = 0; nt2 < 4; nt2++) {
                    int qd = lane >> 3;          // matrix index 0..3
                    int rr = lane & 7;
                    int row = warpN * 64 + nt2 * 16 + (qd >> 1) * 8 + rr;
                    uint32_t bd = sB + SWZ128(row * 128 + ks * 32 + (qd & 1) * 16);
                    asm volatile(
                        "ldmatrix.sync.aligned.m8n8.x4.shared.b16 {%0,%1,%2,%3}, [%4];"
                        : "=r"(bq[nt2][0]), "=r"(bq[nt2][1]), "=r"(bq[nt2][2]), "=r"(bq[nt2][3])
                        : "r"(bd));
                }
                #pragma unroll
                for (int mt = 0; mt < 2; mt++)
                    #pragma unroll
                    for (int nt = 0; nt < 8; nt++) {
                        uint32_t b0 = bq[nt >> 1][(nt & 1) * 2 + 0];
                        uint32_t b1 = bq[nt >> 1][(nt & 1) * 2 + 1];
                        asm volatile(
                            "mma.sync.aligned.m16n8k16.row.col.f32.bf16.bf16.f32 "
                            "{%0,%1,%2,%3}, {%4,%5,%6,%7}, {%8,%9}, {%0,%1,%2,%3};"
                            : "+f"(acc[mt][nt][0]), "+f"(acc[mt][nt][1]),
                              "+f"(acc[mt][nt][2]), "+f"(acc[mt][nt][3])
                            : "r"(a[mt][0]), "r"(a[mt][1]), "r"(a[mt][2]), "r"(a[mt][3]),
                              "r"(b0), "r"(b1));
                    }
            }
            __syncthreads();
        }

        // fold chunk results into per-row top-5 (mask padded cols >= 500)
        const int colBase = cb * BNC + warpN * 64 + (lane & 3) * 2;
        #pragma unroll
        for (int mt = 0; mt < 2; mt++)
            #pragma unroll
            for (int c2 = 0; c2 < 2; c2++)
                #pragma unroll
                for (int nt = 0; nt < 8; nt++)
                    #pragma unroll
                    for (int c1 = 0; c1 < 2; c1++) {
                        float v = acc[mt][nt][c2 * 2 + c1];
                        int col = colBase + nt * 8 + c1;
                        if (col < NROWS && v > t5[mt * 2 + c2][4]) {
                            t5[mt * 2 + c2][4] = v;
                            #pragma unroll
                            for (int j = 4; j > 0; j--) {
                                if (t5[mt * 2 + c2][j] > t5[mt * 2 + c2][j - 1]) {
                                    float x = t5[mt * 2 + c2][j];
                                    t5[mt * 2 + c2][j] = t5[mt * 2 + c2][j - 1];
                                    t5[mt * 2 + c2][j - 1] = x;
                                }
                            }
                        }
                    }
    }

    // dump per-thread top-5s: row x 8 contributors x 5 (20KB, reuses pipeline smem)
    float* dump = (float*)smem;
    const int slot = warpN * 4 + (lane & 3);
    #pragma unroll
    for (int rr = 0; rr < 4; rr++) {
        int row = warpM * 32 + rr * 8 + (lane >> 2);
        #pragma unroll
        for (int j = 0; j < 5; j++)
            dump[row * 40 + slot * 5 + j] = t5[rr][j];
    }
    __syncthreads();

    // final: one thread per row merges 40 candidates -> top-5 mean -> atomicAdd
    if (tid < BM) {
        int gm = mBlock + tid;
        if (gm < MROWS) {
            const float* vals = dump + tid * 40;
            float s0 = -INFINITY, s1 = -INFINITY, s2 = -INFINITY,
                  s3 = -INFINITY, s4 = -INFINITY;
            #pragma unroll
            for (int i = 0; i < 40; i++) {
                float v = vals[i];
                if (v > s4) {
                    s4 = v;
                    if (s4 > s3) { float x = s4; s4 = s3; s3 = x; }
                    if (s3 > s2) { float x = s3; s3 = s2; s2 = x; }
                    if (s2 > s1) { float x = s2; s2 = s1; s1 = x; }
                    if (s1 > s0) { float x = s1; s1 = s0; s0 = x; }
                }
            }
            int q = gm / HW_;
            float val = (s0 + s1 + s2 + s3 + s4) * (1.0f / NK_);
            atomicAdd(&out[(b * Q_ + q) * WAY_ + grp], val);
        }
    }
}

// ---------------------------------------------------------------------------
extern "C" void kernel_launch(void* const* d_in, const int* in_sizes, int n_in,
                              void* d_out, int out_size) {
    const float* input1 = (const float*)d_in[0];   // [2,75,10,10,640]
    const float* input2 = (const float*)d_in[1];   // [2,5,5,10,10,640]
    float* out = (float*)d_out;                    // [2,75,5] = 750

    cudaFuncSetAttribute(fused_gemm_topk_kernel,
                         cudaFuncAttributeMaxDynamicSharedMemorySize, SMEM_TOTAL);

    normalize_kernel<<<(NQTOT + NSTOT + 7) / 8, 256>>>(input1, input2);
    zero_out_kernel<<<3, 256>>>(out);

    dim3 grid((MROWS + BM - 1) / BM, NGRP);        // (59, 10)
    fused_gemm_topk_kernel<<<grid, 256, SMEM_TOTAL>>>(out);
}

// round 5
// speedup vs baseline: 7.3545x; 1.3187x over previous
#include <cuda_runtime.h>
#include <cuda_bf16.h>
#include <math.h>
#include <stdint.h>

// Problem constants
#define B_    2
#define Q_    75
#define WAY_  5
#define SHOT_ 5
#define HW_   100
#define C_    640
#define NK_   5

#define MROWS (Q_*HW_)        // 7500 query patches per b
#define NROWS (WAY_*HW_)      // 500 support patches per group
#define NGRP  (B_*SHOT_)      // 10 groups
#define NQTOT (B_*MROWS)      // 15000
#define NSTOT (NGRP*NROWS)    // 5000

// Normalized bf16 descriptors (static device scratch — allocation-free)
__device__ __nv_bfloat16 g_q16[(size_t)NQTOT * C_];
__device__ __nv_bfloat16 g_s16[(size_t)NSTOT * C_];

__device__ __forceinline__ uint32_t smem_u32(const void* p) {
    uint32_t a;
    asm("{ .reg .u64 t; cvta.to.shared.u64 t, %1; cvt.u32.u64 %0, t; }"
        : "=r"(a) : "l"(p));
    return a;
}

#define SWZ128(o) ((o) ^ (((o) >> 3) & 0x70))

// ---------------------------------------------------------------------------
// Kernel 1: L2-normalize each 640-dim descriptor, cast to bf16.
// One warp per row (20000 rows).
// ---------------------------------------------------------------------------
__global__ void normalize_kernel(const float* __restrict__ q,
                                 const float* __restrict__ s) {
    int warp = (blockIdx.x * blockDim.x + threadIdx.x) >> 5;
    int lane = threadIdx.x & 31;
    if (warp >= NQTOT + NSTOT) return;

    const float* src;
    __nv_bfloat16* dst;
    if (warp < NQTOT) {
        src = q + (size_t)warp * C_;
        dst = g_q16 + (size_t)warp * C_;
    } else {
        int r = warp - NQTOT;
        src = s + (size_t)r * C_;
        dst = g_s16 + (size_t)r * C_;
    }

    const float4* p4 = (const float4*)src;
    float4 v[5];
    float acc = 0.f;
    #pragma unroll
    for (int t = 0; t < 5; t++) {
        v[t] = p4[lane + 32 * t];
        acc += v[t].x * v[t].x + v[t].y * v[t].y + v[t].z * v[t].z + v[t].w * v[t].w;
    }
    #pragma unroll
    for (int o = 16; o; o >>= 1) acc += __shfl_xor_sync(0xFFFFFFFFu, acc, o);
    float inv = rsqrtf(acc);

    #pragma unroll
    for (int t = 0; t < 5; t++) {
        __nv_bfloat162 lo = __float22bfloat162_rn(make_float2(v[t].x * inv, v[t].y * inv));
        __nv_bfloat162 hi = __float22bfloat162_rn(make_float2(v[t].z * inv, v[t].w * inv));
        uint2 pack;
        pack.x = *(uint32_t*)&lo;
        pack.y = *(uint32_t*)&hi;
        *(uint2*)(dst + (size_t)(lane + 32 * t) * 4) = pack;
    }
}

// ---------------------------------------------------------------------------
// Kernel 2: zero the 750-float output (poisoned before timing).
// ---------------------------------------------------------------------------
__global__ void zero_out_kernel(float* __restrict__ out) {
    int i = blockIdx.x * blockDim.x + threadIdx.x;
    if (i < B_ * Q_ * WAY_) out[i] = 0.f;
}

// ---------------------------------------------------------------------------
// Kernel 3: fused bf16 HMMA GEMM (128 x 512 x 640) + streaming top-5 + reduce.
// grid = (59 M-tiles, 10 groups), 256 threads (8 warps as 4x2), 2 CTAs/SM.
// Single flattened 40-stage (4 N-chunks x 10 K-chunks) cp.async pipeline.
// ---------------------------------------------------------------------------
#define BM   128
#define BNC  128           // N chunk
#define BK   64            // K chunk (64 bf16 = 128B rows, SW128)
#define NKC  (C_/BK)       // 10
#define NNC  4             // N chunks (covers 512 padded)
#define NSTG (NNC*NKC)     // 40 pipeline stages

#define SA_OFF(buf) ((buf) * 16384)
#define SB_OFF(buf) (32768 + (buf) * 16384)
#define SMEM_TOTAL  65536

__global__ __launch_bounds__(256, 2)
void fused_gemm_topk_kernel(float* __restrict__ out) {
    extern __shared__ __align__(1024) char smem[];
    const uint32_t sbase = smem_u32(smem);
    const int tid   = threadIdx.x;
    const int lane  = tid & 31;
    const int wid   = tid >> 5;
    const int warpM = wid >> 1;      // 0..3
    const int warpN = wid & 1;       // 0..1

    const int mBlock = blockIdx.x * BM;
    const int z   = blockIdx.y;      // b*5 + group
    const int b   = z / SHOT_;
    const int grp = z % SHOT_;

    const __nv_bfloat16* gA = g_q16 + (size_t)b * MROWS * C_;
    const __nv_bfloat16* gB = g_s16 + (size_t)z * NROWS * C_;

    // running top-5 per owned row: rr -> row = warpM*32 + rr*8 + lane/4
    float t5[4][5];
    #pragma unroll
    for (int r = 0; r < 4; r++)
        #pragma unroll
        for (int j = 0; j < 5; j++) t5[r][j] = -INFINITY;

    // stage loader: stage s = cb*NKC + kc. A 128x64 bf16 + B 128x64 bf16.
    auto load_stage = [&](int s, int buf) {
        const int cb = s / NKC;
        const int kc = s - cb * NKC;
        #pragma unroll
        for (int t = 0; t < 4; t++) {
            int u = tid + t * 256;
            int r = u >> 3, seg = u & 7;
            int gm = mBlock + r;
            uint32_t dst = sbase + SA_OFF(buf) + SWZ128(r * 128 + seg * 16);
            const char* src = (const char*)gA
                + ((size_t)(gm < MROWS ? gm : 0) * C_ + kc * BK) * 2 + seg * 16;
            int sz = (gm < MROWS) ? 16 : 0;
            asm volatile("cp.async.cg.shared.global [%0], [%1], 16, %2;"
                         :: "r"(dst), "l"(src), "r"(sz));
        }
        #pragma unroll
        for (int t = 0; t < 4; t++) {
            int u = tid + t * 256;
            int r = u >> 3, seg = u & 7;
            int gn = cb * BNC + r;
            uint32_t dst = sbase + SB_OFF(buf) + SWZ128(r * 128 + seg * 16);
            const char* src = (const char*)gB
                + ((size_t)(gn < NROWS ? gn : 0) * C_ + kc * BK) * 2 + seg * 16;
            int sz = (gn < NROWS) ? 16 : 0;
            asm volatile("cp.async.cg.shared.global [%0], [%1], 16, %2;"
                         :: "r"(dst), "l"(src), "r"(sz));
        }
        asm volatile("cp.async.commit_group;" ::: "memory");
    };

    float acc[2][8][4];
    #pragma unroll
    for (int mt = 0; mt < 2; mt++)
        #pragma unroll
        for (int nt = 0; nt < 8; nt++)
            #pragma unroll
            for (int c = 0; c < 4; c++) acc[mt][nt][c] = 0.f;

    load_stage(0, 0);

    #pragma unroll 1
    for (int s = 0; s < NSTG; s++) {
        const int buf = s & 1;
        const int cb = s / NKC;
        const int kc = s - cb * NKC;

        if (s + 1 < NSTG) {
            load_stage(s + 1, buf ^ 1);
            asm volatile("cp.async.wait_group 1;" ::: "memory");
        } else {
            asm volatile("cp.async.wait_group 0;" ::: "memory");
        }
        __syncthreads();

        const uint32_t sA = sbase + SA_OFF(buf);
        const uint32_t sB = sbase + SB_OFF(buf);

        #pragma unroll
        for (int ks = 0; ks < 4; ks++) {
            uint32_t a[2][4];
            #pragma unroll
            for (int mt = 0; mt < 2; mt++) {
                int row = warpM * 32 + mt * 16 + (lane & 15);
                uint32_t ad = sA + SWZ128(row * 128 + ks * 32 + (lane >> 4) * 16);
                asm volatile(
                    "ldmatrix.sync.aligned.m8n8.x4.shared.b16 {%0,%1,%2,%3}, [%4];"
                    : "=r"(a[mt][0]), "=r"(a[mt][1]), "=r"(a[mt][2]), "=r"(a[mt][3])
                    : "r"(ad));
            }
            uint32_t bq[4][4];
            #pragma unroll
            for (int nt2 = 0; nt2 < 4; nt2++) {
                int qd = lane >> 3;          // matrix index 0..3
                int rr = lane & 7;
                int row = warpN * 64 + nt2 * 16 + (qd >> 1) * 8 + rr;
                uint32_t bd = sB + SWZ128(row * 128 + ks * 32 + (qd & 1) * 16);
                asm volatile(
                    "ldmatrix.sync.aligned.m8n8.x4.shared.b16 {%0,%1,%2,%3}, [%4];"
                    : "=r"(bq[nt2][0]), "=r"(bq[nt2][1]), "=r"(bq[nt2][2]), "=r"(bq[nt2][3])
                    : "r"(bd));
            }
            #pragma unroll
            for (int mt = 0; mt < 2; mt++)
                #pragma unroll
                for (int nt = 0; nt < 8; nt++) {
                    uint32_t b0 = bq[nt >> 1][(nt & 1) * 2 + 0];
                    uint32_t b1 = bq[nt >> 1][(nt & 1) * 2 + 1];
                    asm volatile(
                        "mma.sync.aligned.m16n8k16.row.col.f32.bf16.bf16.f32 "
                        "{%0,%1,%2,%3}, {%4,%5,%6,%7}, {%8,%9}, {%0,%1,%2,%3};"
                        : "+f"(acc[mt][nt][0]), "+f"(acc[mt][nt][1]),
                          "+f"(acc[mt][nt][2]), "+f"(acc[mt][nt][3])
                        : "r"(a[mt][0]), "r"(a[mt][1]), "r"(a[mt][2]), "r"(a[mt][3]),
                          "r"(b0), "r"(b1));
                }
        }
        __syncthreads();

        // end of an N-chunk: fold acc into per-row top-5, reset acc.
        if (kc == NKC - 1) {
            const int colBase = cb * BNC + warpN * 64 + (lane & 3) * 2;
            #pragma unroll
            for (int mt = 0; mt < 2; mt++)
                #pragma unroll
                for (int c2 = 0; c2 < 2; c2++)
                    #pragma unroll
                    for (int nt = 0; nt < 8; nt++)
                        #pragma unroll
                        for (int c1 = 0; c1 < 2; c1++) {
                            float v = acc[mt][nt][c2 * 2 + c1];
                            int col = colBase + nt * 8 + c1;
                            if (col < NROWS && v > t5[mt * 2 + c2][4]) {
                                t5[mt * 2 + c2][4] = v;
                                #pragma unroll
                                for (int j = 4; j > 0; j--) {
                                    if (t5[mt * 2 + c2][j] > t5[mt * 2 + c2][j - 1]) {
                                        float x = t5[mt * 2 + c2][j];
                                        t5[mt * 2 + c2][j] = t5[mt * 2 + c2][j - 1];
                                        t5[mt * 2 + c2][j - 1] = x;
                                    }
                                }
                            }
                        }
            #pragma unroll
            for (int mt = 0; mt < 2; mt++)
                #pragma unroll
                for (int nt = 0; nt < 8; nt++)
                    #pragma unroll
                    for (int c = 0; c < 4; c++) acc[mt][nt][c] = 0.f;
        }
    }

    // dump per-thread top-5s: row x 8 contributors x 5 (20KB, reuses smem)
    __syncthreads();
    float* dump = (float*)smem;
    const int slot = warpN * 4 + (lane & 3);
    #pragma unroll
    for (int rr = 0; rr < 4; rr++) {
        int row = warpM * 32 + rr * 8 + (lane >> 2);
        #pragma unroll
        for (int j = 0; j < 5; j++)
            dump[row * 40 + slot * 5 + j] = t5[rr][j];
    }
    __syncthreads();

    // final: one thread per row merges 40 candidates -> top-5 mean -> atomicAdd
    if (tid < BM) {
        int gm = mBlock + tid;
        if (gm < MROWS) {
            const float* vals = dump + tid * 40;
            float s0 = -INFINITY, s1 = -INFINITY, s2 = -INFINITY,
                  s3 = -INFINITY, s4 = -INFINITY;
            #pragma unroll
            for (int i = 0; i < 40; i++) {
                float v = vals[i];
                if (v > s4) {
                    s4 = v;
                    if (s4 > s3) { float x = s4; s4 = s3; s3 = x; }
                    if (s3 > s2) { float x = s3; s3 = s2; s2 = x; }
                    if (s2 > s1) { float x = s2; s2 = s1; s1 = x; }
                    if (s1 > s0) { float x = s1; s1 = s0; s0 = x; }
                }
            }
            int q = gm / HW_;
            float val = (s0 + s1 + s2 + s3 + s4) * (1.0f / NK_);
            atomicAdd(&out[(b * Q_ + q) * WAY_ + grp], val);
        }
    }
}

// ---------------------------------------------------------------------------
extern "C" void kernel_launch(void* const* d_in, const int* in_sizes, int n_in,
                              void* d_out, int out_size) {
    const float* input1 = (const float*)d_in[0];   // [2,75,10,10,640]
    const float* input2 = (const float*)d_in[1];   // [2,5,5,10,10,640]
    float* out = (float*)d_out;                    // [2,75,5] = 750

    cudaFuncSetAttribute(fused_gemm_topk_kernel,
                         cudaFuncAttributeMaxDynamicSharedMemorySize, SMEM_TOTAL);

    normalize_kernel<<<(NQTOT + NSTOT + 7) / 8, 256>>>(input1, input2);
    zero_out_kernel<<<3, 256>>>(out);

    dim3 grid((MROWS + BM - 1) / BM, NGRP);        // (59, 10)
    fused_gemm_topk_kernel<<<grid, 256, SMEM_TOTAL>>>(out);
}